// round 11
// baseline (speedup 1.0000x reference)
#include <cuda_runtime.h>
#include <cuda_fp16.h>
#include <cstdint>

// LocallyConnected2d via single-pass fp16 mma.sync m16n8k16 implicit GEMM.
// out[b,o,h,w] = sum_{c,k} patch(x)[b,c,h,w,k] * W[o,c,h,w,k]
// x: [128,64,32,32] f32   weight: [1,64,64,32,32,9] f32   out: [128,64,32,32] f32
//
// R11: R10 with ASTR fixed 264 -> 272 (multiple of 16; cp.async.16 and
//      ldmatrix both require 16B-aligned addresses -> "misaligned address").
//  - CTA = 4 adjacent w positions, 256 CTAs x 512 threads (1/SM)
//  - weights: 36-float contiguous runs per (o,c) -> 9x aligned LDG.128,
//    register-pipelined fp32->fp16 convert (no fp32 smem stage)
//  - K chunks channel-aligned: 8 chunks x 72 kk, padded to 80 (5 k16 steps),
//    B pad rows zeroed once; A pad garbage is harmless (x * 0)
//  - A tile shared across positions: [c][p][ww6][b], ldmatrix rows via LUT
//  - no K-split (16 warps = 4pos x 2M x 2N, full K) -> no reduce
//  - epilogue writes out[b][o][hw0..3] directly as float4 (no transpose pass)

#define BATCH 128
#define CI    64
#define CO    64
#define HGT   32
#define WID   32
#define HWN   1024
#define NCHUNK 8
#define CCH   8            // channels per chunk
#define KKR   72           // real kk per chunk
#define NSTEP 5            // k16 steps (80 kk padded)

#define ASTR   272         // A row stride bytes (128 h + 8 pad; multiple of 16!)
#define AROWS  144         // 8c * 3p * 6ww
#define ASIZE  39168       // 144*272
#define BSTR   168         // B row stride bytes (80 h + 4 pad)
#define BSIZE  43008       // 256 rows * 168
#define OFF_A0 0
#define OFF_A1 39168
#define OFF_B0 78336
#define OFF_B1 121344
#define DYN_BYTES 164352

__device__ __half g_xh[CI * HGT * WID * BATCH];  // 8 MB [c][h][w][b] fp16

// ---------------- helpers ----------------------------------------------------
__device__ __forceinline__ uint32_t smem_u32(const void* p) {
    uint32_t a;
    asm("{ .reg .u64 t; cvta.to.shared.u64 t, %1; cvt.u32.u64 %0, t; }" : "=r"(a) : "l"(p));
    return a;
}
__device__ __forceinline__ void lds64(uint32_t a, uint32_t& lo, uint32_t& hi) {
    asm volatile("ld.shared.v2.b32 {%0,%1}, [%2];" : "=r"(lo), "=r"(hi) : "r"(a));
}
__device__ __forceinline__ void sts32(uint32_t a, uint32_t v) {
    asm volatile("st.shared.b32 [%0], %1;" :: "r"(a), "r"(v) : "memory");
}
__device__ __forceinline__ void sts16(uint32_t a, unsigned short v) {
    asm volatile("st.shared.b16 [%0], %1;" :: "r"(a), "h"(v) : "memory");
}
__device__ __forceinline__ void cp16(uint32_t dst, const void* src, int srcbytes) {
    asm volatile("cp.async.cg.shared.global [%0], [%1], 16, %2;"
                 :: "r"(dst), "l"(src), "r"(srcbytes) : "memory");
}
#define CP_COMMIT() asm volatile("cp.async.commit_group;" ::: "memory")
#define CP_WAIT1()  asm volatile("cp.async.wait_group 1;" ::: "memory")
__device__ __forceinline__ void ldm4t(uint32_t* r, uint32_t addr) {
    asm volatile("ldmatrix.sync.aligned.m8n8.x4.trans.shared.b16 {%0,%1,%2,%3}, [%4];"
                 : "=r"(r[0]), "=r"(r[1]), "=r"(r[2]), "=r"(r[3]) : "r"(addr));
}
__device__ __forceinline__ void mma_f16(float* d, const uint32_t* a, const uint32_t* b) {
    asm volatile("mma.sync.aligned.m16n8k16.row.col.f32.f16.f16.f32 "
                 "{%0,%1,%2,%3}, {%4,%5,%6,%7}, {%8,%9}, {%0,%1,%2,%3};"
                 : "+f"(d[0]), "+f"(d[1]), "+f"(d[2]), "+f"(d[3])
                 : "r"(a[0]), "r"(a[1]), "r"(a[2]), "r"(a[3]), "r"(b[0]), "r"(b[1]));
}

// ---------------- Kernel 1: x -> g_xh[c][h][w][b] fp16 -----------------------
__global__ __launch_bounds__(256)
void prep_x_kernel(const float* __restrict__ x) {
    const int c = blockIdx.x >> 5;
    const int h = blockIdx.x & 31;
    __shared__ float tile[WID * 129];
    const int tid = threadIdx.x;
#pragma unroll
    for (int it = 0; it < 16; it++) {
        const int idx = it * 256 + tid;
        const int b = idx >> 5, w = idx & 31;
        tile[w * 129 + b] = x[(((size_t)b * CI + c) * HGT + h) * WID + w];
    }
    __syncthreads();
#pragma unroll
    for (int it = 0; it < 16; it++) {
        const int idx = it * 256 + tid;
        const int w = idx >> 7, b = idx & 127;
        g_xh[(((size_t)c * HGT + h) * WID + w) * BATCH + b] = __float2half_rn(tile[w * 129 + b]);
    }
}

// ---------------- Kernel 2: main MMA GEMM ------------------------------------
__global__ __launch_bounds__(512, 1)
void lc2d_mma_kernel(const float* __restrict__ wgt, float* __restrict__ out) {
    extern __shared__ __align__(16) char dyns[];
    __shared__ uint32_t lut[80];     // kk -> A row byte offset (row*ASTR)

    const uint32_t dynb = smem_u32(dyns);
    const int h      = blockIdx.x >> 3;
    const int w0     = (blockIdx.x & 7) << 2;
    const int hwbase = h * WID + w0;
    const int tid  = threadIdx.x;
    const int wrp  = tid >> 5;
    const int lane = tid & 31;

    const int pos = wrp & 3;
    const int mh  = (wrp >> 2) & 1;
    const int nh  = wrp >> 3;

    const int lm_r    = lane & 7;
    const int lm_koff = (lane & 16) ? 8 : 0;
    const int lm_moff = (lane & 8) ? 8 : 0;

    // ---- init: LUT + zero B pad words (both stages) ----------------------
    if (tid < 80) {
        int v = 0;
        if (tid < KKR) {
            const int c  = tid / 9;
            const int r9 = tid - c * 9;
            const int p  = r9 / 3;
            const int q  = r9 - p * 3;
            v = ((c * 3 + p) * 6 + q) * ASTR;
        }
        lut[tid] = (uint32_t)v;
    }
#pragma unroll
    for (int it = 0; it < 4; it++) {
        const int u = it * 512 + tid;        // 2048 pad words
        const int s   = u >> 10;
        const int row = (u >> 2) & 255;
        const int ws  = u & 3;
        sts32(dynb + (s ? OFF_B1 : OFF_B0) + (uint32_t)row * BSTR + 128 + 4 + ws * 8, 0u);
    }
    __syncthreads();

    float acc[4][4][4];
#pragma unroll
    for (int mf = 0; mf < 4; mf++)
#pragma unroll
        for (int nf = 0; nf < 4; nf++)
#pragma unroll
            for (int c = 0; c < 4; c++) acc[mf][nf][c] = 0.0f;

    // ---- B staging state: thread = (o, cc); 36 contiguous floats per chunk
    const int o_b  = tid & 63;
    const int cc_b = tid >> 6;               // 0..7
    const float* srcB = wgt + ((size_t)o_b * CI + cc_b) * (HWN * 9)
                            + (size_t)hwbase * 9;
    uint32_t boff[9];                        // byte offset of kk=cc*9+k within row
#pragma unroll
    for (int k = 0; k < 9; k++) {
        const int kk = cc_b * 9 + k;
        const int g  = kk >> 4;
        const int wi = (kk >> 1) & 7;
        const int np = ((wi & 3) << 1) | (wi >> 2);
        boff[k] = (uint32_t)(g * 32 + np * 4 + (kk & 1) * 2);
    }
    const uint32_t browb = (uint32_t)o_b * BSTR;

    float vv[36];

    auto ldgB1 = [&]() {                     // floats 0..15
#pragma unroll
        for (int i = 0; i < 4; i++) {
            const float4 t = reinterpret_cast<const float4*>(srcB)[i];
            vv[4*i] = t.x; vv[4*i+1] = t.y; vv[4*i+2] = t.z; vv[4*i+3] = t.w;
        }
    };
    auto ldgB2 = [&]() {                     // floats 16..35
#pragma unroll
        for (int i = 4; i < 9; i++) {
            const float4 t = reinterpret_cast<const float4*>(srcB)[i];
            vv[4*i] = t.x; vv[4*i+1] = t.y; vv[4*i+2] = t.z; vv[4*i+3] = t.w;
        }
    };
    auto cvtB = [&](uint32_t bb) {           // bb = dynb + OFF_B(stage)
        const uint32_t base0 = bb + browb;
#pragma unroll
        for (int p = 0; p < 4; p++)
#pragma unroll
            for (int k = 0; k < 9; k++) {
                const __half hv = __float2half_rn(vv[p * 9 + k]);
                sts16(base0 + (uint32_t)p * (64 * BSTR) + boff[k],
                      __half_as_ushort(hv));
            }
    };
    auto cpA = [&](int jn, uint32_t ab) {    // ab = dynb + OFF_A(stage)
#pragma unroll
        for (int it = 0; it < 5; it++) {
            const int u = it * 512 + tid;
            if (u < AROWS * 16) {
                const int row = u >> 4;
                const int seg = u & 15;
                const int c   = row / 18;
                const int rem = row - c * 18;
                const int p   = rem / 6;
                const int ww  = rem - p * 6;
                const int hh  = h + p - 1;
                const int wg  = w0 + ww - 1;
                const bool ok = (hh >= 0 && hh < HGT && wg >= 0 && wg < WID);
                const int xr  = ((jn * CCH + c) * HGT + (ok ? hh : 0)) * WID + (ok ? wg : 0);
                cp16(ab + (uint32_t)row * ASTR + (uint32_t)seg * 16,
                     g_xh + (size_t)xr * BATCH + seg * 8, ok ? 16 : 0);
            }
        }
    };

    // ---- prologue --------------------------------------------------------
    ldgB1(); ldgB2();
    srcB += (size_t)CCH * (HWN * 9);
    cpA(0, dynb + OFF_A0);
    CP_COMMIT();

    // ---- mainloop --------------------------------------------------------
    for (int j = 0; j < NCHUNK; j++) {
        const int s = j & 1;
        const uint32_t ab = dynb + (s ? OFF_A1 : OFF_A0);
        const uint32_t bb = dynb + (s ? OFF_B1 : OFF_B0);
        const uint32_t abn = dynb + (s ? OFF_A0 : OFF_A1);

        cvtB(bb);                            // fp16 B tile for chunk j
        if (j + 1 < NCHUNK) {
            ldgB1();                         // chunk j+1 first half (latency hidden)
            cpA(j + 1, abn);
        }
        CP_COMMIT();
        CP_WAIT1();
        __syncthreads();                     // A(j) + all warps' B tile visible

        // compute chunk j
        const uint32_t acb = ab + (uint32_t)pos * ASTR
                           + (uint32_t)(mh * 64 + lm_moff) * 2;
        const uint32_t bcb = bb + (uint32_t)(pos * 64 + nh * 32 + (lane >> 2)) * BSTR
                           + (uint32_t)(lane & 3) * 8;
#pragma unroll
        for (int st = 0; st < NSTEP; st++) {
            const int kk = st * 16 + lm_koff + lm_r;
            const uint32_t lrow = lut[kk];
            uint32_t bfr[4][2];
#pragma unroll
            for (int nf = 0; nf < 4; nf++)
                lds64(bcb + (uint32_t)nf * (8 * BSTR) + (uint32_t)st * 32,
                      bfr[nf][0], bfr[nf][1]);
#pragma unroll
            for (int mf = 0; mf < 4; mf++) {
                uint32_t a[4];
                ldm4t(a, acb + lrow + (uint32_t)mf * 32);
#pragma unroll
                for (int nf = 0; nf < 4; nf++)
                    mma_f16(acc[mf][nf], a, bfr[nf]);
            }
        }
        if (j + 1 < NCHUNK) {
            ldgB2();                         // chunk j+1 second half
            srcB += (size_t)CCH * (HWN * 9);
        }
        __syncthreads();                     // chunk consumed before overwrite
    }

    // ---- epilogue: two b-slices through smem, direct float4 stores -------
    float* sl = reinterpret_cast<float*>(dyns);   // [b_local 64][o 64][pos 4]
#pragma unroll
    for (int slice = 0; slice < 2; slice++) {
        if (mh == slice) {
#pragma unroll
            for (int mf = 0; mf < 4; mf++)
#pragma unroll
                for (int nf = 0; nf < 4; nf++)
#pragma unroll
                    for (int c = 0; c < 4; c++) {
                        const int bl = mf * 16 + (lane >> 2) + ((c & 2) ? 8 : 0);
                        const int o  = nh * 32 + nf * 8 + ((lane & 3) << 1) + (c & 1);
                        sl[(bl * 64 + o) * 4 + pos] = acc[mf][nf][c];
                    }
        }
        __syncthreads();
#pragma unroll
        for (int it = 0; it < 8; it++) {
            const int idx = it * 512 + tid;       // 4096 float4
            const int bl = idx >> 6;
            const int o  = idx & 63;
            const float4 v = reinterpret_cast<const float4*>(sl)[idx];
            *reinterpret_cast<float4*>(
                out + ((size_t)(slice * 64 + bl) * CO + o) * HWN + hwbase) = v;
        }
        __syncthreads();
    }
}

// ---------------- launch -----------------------------------------------------
extern "C" void kernel_launch(void* const* d_in, const int* in_sizes, int n_in,
                              void* d_out, int out_size) {
    const float* x   = (const float*)d_in[0];
    const float* wgt = (const float*)d_in[1];
    float* out = (float*)d_out;
    (void)in_sizes; (void)n_in; (void)out_size;

    cudaFuncSetAttribute(lc2d_mma_kernel, cudaFuncAttributeMaxDynamicSharedMemorySize, DYN_BYTES);

    prep_x_kernel<<<CI * HGT, 256>>>(x);
    lc2d_mma_kernel<<<256, 512, DYN_BYTES>>>(wgt, out);
}

// round 12
// speedup vs baseline: 1.2791x; 1.2791x over previous
#include <cuda_runtime.h>
#include <cuda_fp16.h>
#include <cstdint>

// LocallyConnected2d via single-pass fp16 mma.sync m16n8k16 implicit GEMM.
// out[b,o,h,w] = sum_{c,k} patch(x)[b,c,h,w,k] * W[o,c,h,w,k]
// x: [128,64,32,32] f32   weight: [1,64,64,32,32,9] f32   out: [128,64,32,32] f32
//
// R12 = R9 structure (per-hw CTA, 2 CTAs/SM, lane=kk coalesced B loads) with
// the per-chunk overhead folded under the HMMA shadow:
//  - B(j+1): LDG fp32 -> regs -> cvt -> sts16 into the OTHER stage buffer,
//    interleaved with compute(j). fp32 B smem stage + lds64f round-trip gone.
//  - ONE __syncthreads per chunk (was 3).
//  - A(j+1) via cp.async issued before compute(j), wait_group 0 at iter top.

#define BATCH 128
#define CI    64
#define CO    64
#define HGT   32
#define WID   32
#define HWN   1024
#define KC    64
#define NCHUNK 9

#define ASTRH  272                  // A fp16 row stride bytes (128 + 16 pad)
#define BSTRH  144                  // B fp16 row stride bytes (128 + 16 pad)
#define OFF_BH 17408                // 64*272
#define STAGE  26624                // 17408 + 64*144
#define DYN_BYTES (2 * STAGE)

#define OSTRIDE 2359296             // 4*CI*HWN*9 floats between o and o+4

__device__ __half g_xh[CI * HGT * WID * BATCH];  // 8 MB  [c][h][w][b] fp16
__device__ float  g_outT[HWN * CO * BATCH];      // 32 MB [hw][o][b]

// ---------------- helpers ----------------------------------------------------
__device__ __forceinline__ uint32_t smem_u32(const void* p) {
    uint32_t a;
    asm("{ .reg .u64 t; cvta.to.shared.u64 t, %1; cvt.u32.u64 %0, t; }" : "=r"(a) : "l"(p));
    return a;
}
__device__ __forceinline__ void lds64(uint32_t a, uint32_t& lo, uint32_t& hi) {
    asm volatile("ld.shared.v2.b32 {%0,%1}, [%2];" : "=r"(lo), "=r"(hi) : "r"(a));
}
__device__ __forceinline__ void sts16(uint32_t a, unsigned short v) {
    asm volatile("st.shared.b16 [%0], %1;" :: "r"(a), "h"(v) : "memory");
}
__device__ __forceinline__ void cp16(uint32_t dst, const void* src, int srcbytes) {
    asm volatile("cp.async.cg.shared.global [%0], [%1], 16, %2;"
                 :: "r"(dst), "l"(src), "r"(srcbytes) : "memory");
}
#define CP_COMMIT() asm volatile("cp.async.commit_group;" ::: "memory")
#define CP_WAIT0()  asm volatile("cp.async.wait_group 0;" ::: "memory")
__device__ __forceinline__ void ldm4t(uint32_t* r, uint32_t addr) {
    asm volatile("ldmatrix.sync.aligned.m8n8.x4.trans.shared.b16 {%0,%1,%2,%3}, [%4];"
                 : "=r"(r[0]), "=r"(r[1]), "=r"(r[2]), "=r"(r[3]) : "r"(addr));
}
__device__ __forceinline__ void mma_f16(float* d, const uint32_t* a, const uint32_t* b) {
    asm volatile("mma.sync.aligned.m16n8k16.row.col.f32.f16.f16.f32 "
                 "{%0,%1,%2,%3}, {%4,%5,%6,%7}, {%8,%9}, {%0,%1,%2,%3};"
                 : "+f"(d[0]), "+f"(d[1]), "+f"(d[2]), "+f"(d[3])
                 : "r"(a[0]), "r"(a[1]), "r"(a[2]), "r"(a[3]), "r"(b[0]), "r"(b[1]));
}

// ---------------- Kernel 1: x -> g_xh[c][h][w][b] fp16 -----------------------
__global__ __launch_bounds__(256)
void prep_x_kernel(const float* __restrict__ x) {
    const int c = blockIdx.x >> 5;
    const int h = blockIdx.x & 31;
    __shared__ float tile[WID * 129];
    const int tid = threadIdx.x;
#pragma unroll
    for (int it = 0; it < 16; it++) {
        const int idx = it * 256 + tid;
        const int b = idx >> 5, w = idx & 31;
        tile[w * 129 + b] = x[(((size_t)b * CI + c) * HGT + h) * WID + w];
    }
    __syncthreads();
#pragma unroll
    for (int it = 0; it < 16; it++) {
        const int idx = it * 256 + tid;
        const int w = idx >> 7, b = idx & 127;
        g_xh[(((size_t)c * HGT + h) * WID + w) * BATCH + b] = __float2half_rn(tile[w * 129 + b]);
    }
}

// ---------------- Kernel 2: main MMA GEMM ------------------------------------
__global__ __launch_bounds__(256, 2)
void lc2d_mma_kernel(const float* __restrict__ wgt) {
    extern __shared__ __align__(16) char dyns[];
    __shared__ int rowsAll[NCHUNK * KC];

    const uint32_t dynb = smem_u32(dyns);
    const int hw  = blockIdx.x;
    const int h   = hw >> 5;
    const int w   = hw & 31;
    const int tid = threadIdx.x;
    const int wrp = tid >> 5;
    const int lane = tid & 31;

    const int wm = (wrp & 1) * 64;          // M offset
    const int wn = ((wrp >> 1) & 1) * 32;   // N offset
    const int wk = wrp >> 2;                // K-split half (kk 0..31 vs 32..63)

    const int lm_r    = lane & 7;
    const int lm_koff = (lane & 16) ? 8 : 0;
    const int lm_moff = (lane & 8) ? 8 : 0;

    // ---- precompute kk -> x row for all chunks ---------------------------
    for (int t = tid; t < NCHUNK * KC; t += 256) {
        const int c  = t / 9;
        const int r9 = t - c * 9;
        const int p  = r9 / 3;
        const int q  = r9 - p * 3;
        const int hh = h + p - 1;
        const int ww = w + q - 1;
        rowsAll[t] = (hh < 0 || hh >= HGT || ww < 0 || ww >= WID)
                   ? -1 : ((c * HGT + hh) * WID + ww);
    }
    __syncthreads();

    float acc[4][4][4];
#pragma unroll
    for (int mf = 0; mf < 4; mf++)
#pragma unroll
        for (int nf = 0; nf < 4; nf++)
#pragma unroll
            for (int c = 0; c < 4; c++) acc[mf][nf][c] = 0.0f;

    // ---- B staging state: lane = kk (fixed), o = (tid>>6) + 4*i ----------
    const int kkB = tid & 63;
    int kB = kkB % 9;
    const float* srcB = wgt + ((size_t)(tid >> 6) * CI + kkB / 9) * (HWN * 9)
                            + (size_t)hw * 9 + kB;
    // fp16 dst: word perm pairs (k, k+4) adjacent within 16-groups
    const uint32_t wiB = (uint32_t)((kkB >> 1) & 7);
    const uint32_t npB = ((wiB & 3) << 1) | (wiB >> 2);
    const uint32_t bDst = OFF_BH + (uint32_t)(tid >> 6) * BSTRH
                        + (uint32_t)((kkB >> 4) * 32 + npB * 4 + (kkB & 1) * 2);
    // A staging: seg = tid&15 fixed, kk = (tid>>4) + 16*it
    const int segA = tid & 15;
    const int kk0A = tid >> 4;

    float vv[8];

    auto ldgB = [&](int half) {              // load 8 o-values for next chunk
#pragma unroll
        for (int i = 0; i < 8; i++)
            vv[i] = srcB[(size_t)(half * 8 + i) * OSTRIDE];
    };
    auto cvtsts = [&](uint32_t sbn, int half) {
        const uint32_t base = sbn + bDst + (uint32_t)half * (8 * 4 * BSTRH);
#pragma unroll
        for (int i = 0; i < 8; i++)
            sts16(base + (uint32_t)i * (4 * BSTRH),
                  __half_as_ushort(__float2half_rn(vv[i])));
    };
    auto advB = [&]() {                      // kk += 64 => k += 1, carry at 9
        kB += 1;
        if (kB == 9) { kB = 0; srcB += (8 * HWN * 9 - 8); }
        else         {         srcB += (7 * HWN * 9 + 1); }
    };
    auto cpA = [&](int jn, uint32_t ab) {
#pragma unroll
        for (int it = 0; it < 4; it++) {
            const int kk  = kk0A + it * 16;
            const int row = rowsAll[jn * KC + kk];
            const __half* src = g_xh + (size_t)(row < 0 ? 0 : row) * BATCH + segA * 8;
            cp16(ab + (uint32_t)kk * ASTRH + (uint32_t)segA * 16, src, row < 0 ? 0 : 16);
        }
    };

    // ---- prologue: stage chunk 0 completely ------------------------------
    cpA(0, dynb);
    CP_COMMIT();
    ldgB(0); cvtsts(dynb, 0);
    ldgB(1); cvtsts(dynb, 1);
    advB();

    // ---- mainloop: ONE sync per chunk ------------------------------------
    for (int j = 0; j < NCHUNK; j++) {
        const uint32_t sb  = dynb + (uint32_t)(j & 1) * STAGE;
        const uint32_t sbn = dynb + (uint32_t)((j + 1) & 1) * STAGE;
        const bool more = (j + 1 < NCHUNK);

        CP_WAIT0();
        __syncthreads();          // A(j) + all warps' B(j) sts16 visible;
                                  // also: everyone done reading buffers (j-1)

        if (more) {
            cpA(j + 1, sbn);      // async A for next chunk
            CP_COMMIT();
            ldgB(0);              // B next chunk, first 8 o (latency -> compute)
        }

        // ---- compute step 0 (this warp's first k16) ----------------------
#pragma unroll
        for (int s = 0; s < 2; s++) {
            const int kk0 = wk * 32 + s * 16;
            const uint32_t arow = sb + (uint32_t)(kk0 + lm_koff + lm_r) * ASTRH;
            uint32_t a[4][4];
#pragma unroll
            for (int mf = 0; mf < 4; mf++)
                ldm4t(a[mf], arow + (uint32_t)(wm + mf * 16 + lm_moff) * 2);
            const uint32_t rB = sb + OFF_BH + (uint32_t)(wn + (lane >> 2)) * BSTRH
                              + (uint32_t)((kk0 >> 4) * 32) + (uint32_t)(lane & 3) * 8;
            uint32_t bfr[4][2];
#pragma unroll
            for (int nf = 0; nf < 4; nf++)
                lds64(rB + (uint32_t)nf * (8 * BSTRH), bfr[nf][0], bfr[nf][1]);
#pragma unroll
            for (int mf = 0; mf < 4; mf++)
#pragma unroll
                for (int nf = 0; nf < 4; nf++)
                    mma_f16(acc[mf][nf], a[mf], bfr[nf]);

            // interleave next-chunk B work under the HMMA shadow
            if (more) {
                if (s == 0) { cvtsts(sbn, 0); ldgB(1); }
                else        { cvtsts(sbn, 1); advB(); }
            }
        }
        __syncthreads();          // (end-of-iter barrier merged w/ next top:
                                  // kept to order compute(j) before sts16(j+2)
                                  // wait; actually top sync covers it)
    }

    // ---- epilogue: K-split reduce via smem, coalesced store --------------
    float* sOut = reinterpret_cast<float*>(dyns);   // [o][b], stride 132
    if (wk == 1) {
#pragma unroll
        for (int mf = 0; mf < 4; mf++)
#pragma unroll
            for (int nf = 0; nf < 4; nf++)
#pragma unroll
                for (int c = 0; c < 4; c++) {
                    const int b = wm + mf * 16 + (lane >> 2) + ((c & 2) ? 8 : 0);
                    const int o = wn + nf * 8 + ((lane & 3) << 1) + (c & 1);
                    sOut[o * 132 + b] = acc[mf][nf][c];
                }
    }
    __syncthreads();
    if (wk == 0) {
#pragma unroll
        for (int mf = 0; mf < 4; mf++)
#pragma unroll
            for (int nf = 0; nf < 4; nf++)
#pragma unroll
                for (int c = 0; c < 4; c++) {
                    const int b = wm + mf * 16 + (lane >> 2) + ((c & 2) ? 8 : 0);
                    const int o = wn + nf * 8 + ((lane & 3) << 1) + (c & 1);
                    sOut[o * 132 + b] += acc[mf][nf][c];
                }
    }
    __syncthreads();

    float* dst = g_outT + (size_t)hw * (CO * BATCH);
#pragma unroll
    for (int it = 0; it < 8; it++) {
        const int idx = it * 256 + tid;       // 2048 float4
        const int o  = idx >> 5;
        const int b4 = (idx & 31) << 2;
        const float4 v = *reinterpret_cast<const float4*>(sOut + o * 132 + b4);
        *reinterpret_cast<float4*>(dst + o * BATCH + b4) = v;
    }
}

// ---------------- Kernel 3: g_outT[hw][o][b] -> out[b][o][hw] ----------------
__global__ __launch_bounds__(256)
void out_transpose_kernel(float* __restrict__ out) {
    const int o   = blockIdx.x >> 5;
    const int hw0 = (blockIdx.x & 31) * 32;
    __shared__ float tile[BATCH * 33];
    const int tid = threadIdx.x;
#pragma unroll
    for (int it = 0; it < 16; it++) {
        const int idx = it * 256 + tid;
        const int i = idx >> 7, b = idx & 127;
        tile[b * 33 + i] = g_outT[((size_t)(hw0 + i) * CO + o) * BATCH + b];
    }
    __syncthreads();
#pragma unroll
    for (int it = 0; it < 16; it++) {
        const int idx = it * 256 + tid;
        const int b = idx >> 5, i = idx & 31;
        out[((size_t)b * CO + o) * HWN + hw0 + i] = tile[b * 33 + i];
    }
}

// ---------------- launch -----------------------------------------------------
extern "C" void kernel_launch(void* const* d_in, const int* in_sizes, int n_in,
                              void* d_out, int out_size) {
    const float* x   = (const float*)d_in[0];
    const float* wgt = (const float*)d_in[1];
    float* out = (float*)d_out;
    (void)in_sizes; (void)n_in; (void)out_size;

    cudaFuncSetAttribute(lc2d_mma_kernel, cudaFuncAttributeMaxDynamicSharedMemorySize, DYN_BYTES);

    prep_x_kernel<<<CI * HGT, 256>>>(x);
    lc2d_mma_kernel<<<HWN, 256, DYN_BYTES>>>(wgt);
    out_transpose_kernel<<<CO * 32, 256>>>(out);
}